// round 4
// baseline (speedup 1.0000x reference)
#include <cuda_runtime.h>
#include <cstdint>

// Problem constants (fixed by reference setup_inputs)
#define BATCH 16
#define NPTS 131072
#define NCH 6
#define KSEL 1024

#define CTAS_PER_B 8
#define NPC (NPTS / CTAS_PER_B)   // 16384 points per CTA
#define THREADS 512
#define PPT (NPC / THREADS)       // 32 points per thread
#define NWARPS (THREADS / 32)     // 16

// Per-iteration communication slots (pre-zeroed each launch by init kernel).
// packed = (float_bits(dist) << 32) | (~idx)  -> atomicMax picks max dist,
// smallest idx on ties (matches jnp.argmax first-occurrence).
__device__ unsigned long long g_slot[BATCH][KSEL];
__device__ unsigned int       g_arrive[BATCH][KSEL];

__global__ void fps_init_kernel() {
    int i = blockIdx.x * blockDim.x + threadIdx.x;
    if (i < BATCH * KSEL) {
        (&g_slot[0][0])[i]   = 0ULL;
        (&g_arrive[0][0])[i] = 0u;
    }
}

__device__ __forceinline__ unsigned int ld_acq_u32(const unsigned int* p) {
    unsigned int v;
    asm volatile("ld.acquire.gpu.global.u32 %0, [%1];" : "=r"(v) : "l"(p) : "memory");
    return v;
}
__device__ __forceinline__ unsigned long long ld_acq_u64(const unsigned long long* p) {
    unsigned long long v;
    asm volatile("ld.acquire.gpu.global.u64 %0, [%1];" : "=l"(v) : "l"(p) : "memory");
    return v;
}

// Distance matching LLVM's contraction of the left-associated sum
//   ((dx*dx + dy*dy) + dz*dz):
// inner fadd fuses its FIRST fmul operand -> fma(dx,dx, round(dy*dy)),
// outer fadd fuses its fmul operand      -> fma(dz,dz, inner).
__device__ __forceinline__ void upd_point(float x, float y, float z,
                                          float qx, float qy, float qz,
                                          float& dj, float& best, unsigned& bidx,
                                          unsigned idx) {
    float dx = __fadd_rn(x, -qx);
    float dy = __fadd_rn(y, -qy);
    float dz = __fadd_rn(z, -qz);
    float d  = __fmaf_rn(dz, dz, __fmaf_rn(dx, dx, __fmul_rn(dy, dy)));
    float nd = fminf(dj, d);
    dj = nd;
    if (nd > best) { best = nd; bidx = idx; }   // strict > keeps smallest idx
}

__global__ __launch_bounds__(THREADS, 1)
void fps_kernel(const float* __restrict__ pts, float* __restrict__ out) {
    extern __shared__ float sh[];
    float* sx = sh;
    float* sy = sh + NPC;
    float* sz = sh + 2 * NPC;
    __shared__ unsigned long long sred[NWARPS];
    __shared__ float sq[3];
    __shared__ unsigned int sidx;

    const int tid = threadIdx.x;
    const int b   = blockIdx.x / CTAS_PER_B;
    const int c   = blockIdx.x % CTAS_PER_B;
    const float* base = pts + (size_t)b * NPTS * NCH;
    const int p0 = c * NPC;

    // Stage this CTA's xyz slice into SMEM (one-time, ~1.5 MB/CTA from HBM).
    for (int i = tid; i < NPC; i += THREADS) {
        const float* r = base + (size_t)(p0 + i) * NCH;
        sx[i] = r[0];
        sy[i] = r[1];
        sz[i] = r[2];
    }

    // Running min-distances live in registers.
    float dist[PPT];
#pragma unroll
    for (int j = 0; j < PPT; ++j) dist[j] = __int_as_float(0x7f800000); // +inf

    // First selected point is index 0 (deterministic start).
    float qx = base[0], qy = base[1], qz = base[2];
    if (c == 0 && tid < NCH) {
        out[(size_t)b * KSEL * NCH + tid] = base[tid];
    }
    __syncthreads();

    const int myBase = tid * PPT;
    const int lane = tid & 31;
    const int warp = tid >> 5;

    for (int it = 1; it < KSEL; ++it) {
        // --- distance update + local argmax over this thread's 32 points ---
        float best = -1.0f;
        unsigned bidx = 0;
#pragma unroll
        for (int u = 0; u < PPT; u += 4) {
            float4 x4 = *reinterpret_cast<const float4*>(&sx[myBase + u]);
            float4 y4 = *reinterpret_cast<const float4*>(&sy[myBase + u]);
            float4 z4 = *reinterpret_cast<const float4*>(&sz[myBase + u]);
            unsigned gi = (unsigned)(p0 + myBase + u);
            upd_point(x4.x, y4.x, z4.x, qx, qy, qz, dist[u + 0], best, bidx, gi + 0);
            upd_point(x4.y, y4.y, z4.y, qx, qy, qz, dist[u + 1], best, bidx, gi + 1);
            upd_point(x4.z, y4.z, z4.z, qx, qy, qz, dist[u + 2], best, bidx, gi + 2);
            upd_point(x4.w, y4.w, z4.w, qx, qy, qz, dist[u + 3], best, bidx, gi + 3);
        }

        // Pack: high 32 = dist bits (dist >= 0 so uint order == float order),
        // low 32 = ~idx so max prefers the SMALLEST index on ties.
        unsigned long long pk =
            ((unsigned long long)__float_as_uint(best) << 32) |
            (unsigned long long)(~bidx);

        // --- warp reduce ---
#pragma unroll
        for (int off = 16; off > 0; off >>= 1) {
            unsigned long long o = __shfl_down_sync(0xffffffffu, pk, off);
            if (o > pk) pk = o;
        }
        if (lane == 0) sred[warp] = pk;
        __syncthreads();

        // --- CTA reduce (warp 0) + cross-CTA combine via L2 atomics ---
        if (warp == 0) {
            unsigned long long v = (lane < NWARPS) ? sred[lane] : 0ULL;
#pragma unroll
            for (int off = 8; off > 0; off >>= 1) {
                unsigned long long o = __shfl_down_sync(0xffffffffu, v, off);
                if (o > v) v = o;
            }
            if (lane == 0) {
                atomicMax(&g_slot[b][it], v);
                __threadfence();
                atomicAdd(&g_arrive[b][it], 1u);
                // Wait until all 8 CTAs of this batch contributed.
                while (ld_acq_u32(&g_arrive[b][it]) < CTAS_PER_B) { }
                unsigned long long w = ld_acq_u64(&g_slot[b][it]);
                unsigned widx = ~(unsigned)(w & 0xffffffffULL);
                const float* r = base + (size_t)widx * NCH;
                sq[0] = r[0];
                sq[1] = r[1];
                sq[2] = r[2];
                sidx  = widx;
            }
        }
        __syncthreads();

        qx = sq[0]; qy = sq[1]; qz = sq[2];

        // One CTA per batch writes the output row for this iteration.
        if (c == 0 && tid < NCH) {
            out[((size_t)b * KSEL + it) * NCH + tid] =
                base[(size_t)sidx * NCH + tid];
        }
    }
}

extern "C" void kernel_launch(void* const* d_in, const int* in_sizes, int n_in,
                              void* d_out, int out_size) {
    const float* pts = (const float*)d_in[0];
    float* out = (float*)d_out;

    static bool attr_set = false;
    if (!attr_set) {
        cudaFuncSetAttribute(fps_kernel,
                             cudaFuncAttributeMaxDynamicSharedMemorySize,
                             3 * NPC * sizeof(float));
        attr_set = true;
    }

    fps_init_kernel<<<(BATCH * KSEL + 255) / 256, 256>>>();
    fps_kernel<<<BATCH * CTAS_PER_B, THREADS, 3 * NPC * sizeof(float)>>>(pts, out);
}

// round 5
// speedup vs baseline: 2.9540x; 2.9540x over previous
#include <cuda_runtime.h>
#include <cstdint>

// Problem constants (fixed by reference setup_inputs)
#define BATCH 16
#define NPTS 131072
#define NCH 6
#define KSEL 1024

#define CTAS_PER_B 8
#define NPC (NPTS / CTAS_PER_B)   // 16384 points per CTA
#define THREADS 512
#define PPT (NPC / THREADS)       // 32 points per thread
#define NGROUPS (PPT / 4)         // 8 float4-groups per thread
#define NWARPS (THREADS / 32)     // 16

__device__ unsigned long long g_slot[BATCH][KSEL];
__device__ unsigned int       g_arrive[BATCH][KSEL];

__global__ void fps_init_kernel() {
    int i = blockIdx.x * blockDim.x + threadIdx.x;
    if (i < BATCH * KSEL) {
        (&g_slot[0][0])[i]   = 0ULL;
        (&g_arrive[0][0])[i] = 0u;
    }
}

__device__ __forceinline__ unsigned int ld_acq_u32(const unsigned int* p) {
    unsigned int v;
    asm volatile("ld.acquire.gpu.global.u32 %0, [%1];" : "=r"(v) : "l"(p) : "memory");
    return v;
}
__device__ __forceinline__ unsigned long long ld_acq_u64(const unsigned long long* p) {
    unsigned long long v;
    asm volatile("ld.acquire.gpu.global.u64 %0, [%1];" : "=l"(v) : "l"(p) : "memory");
    return v;
}

// ---- packed f32x2 helpers (per-lane IEEE rn, bit-identical to scalar) ----
__device__ __forceinline__ unsigned long long add2(unsigned long long a, unsigned long long b) {
    unsigned long long r;
    asm("add.rn.f32x2 %0, %1, %2;" : "=l"(r) : "l"(a), "l"(b));
    return r;
}
__device__ __forceinline__ unsigned long long mul2(unsigned long long a, unsigned long long b) {
    unsigned long long r;
    asm("mul.rn.f32x2 %0, %1, %2;" : "=l"(r) : "l"(a), "l"(b));
    return r;
}
__device__ __forceinline__ unsigned long long fma2(unsigned long long a, unsigned long long b,
                                                   unsigned long long c) {
    unsigned long long r;
    asm("fma.rn.f32x2 %0, %1, %2, %3;" : "=l"(r) : "l"(a), "l"(b), "l"(c));
    return r;
}
__device__ __forceinline__ void unpack2(float& lo, float& hi, unsigned long long v) {
    asm("mov.b64 {%0, %1}, %2;" : "=f"(lo), "=f"(hi) : "l"(v));
}
__device__ __forceinline__ unsigned long long bcast2(float v) {
    unsigned long long r;
    asm("mov.b64 %0, {%1, %1};" : "=l"(r) : "f"(v));
    return r;
}

// Distance formula (FROZEN, bit-exact vs reference):
//   d = fma(dz,dz, fma(dx,dx, dy*dy)),  dx = x + (-qx) etc.

__global__ __launch_bounds__(THREADS, 1)
void fps_kernel(const float* __restrict__ pts, float* __restrict__ out) {
    extern __shared__ float sh[];
    float* sx = sh;
    float* sy = sh + NPC;
    float* sz = sh + 2 * NPC;
    __shared__ unsigned long long sred[NWARPS];
    __shared__ float sq[3];
    __shared__ unsigned int sidx;

    const int tid = threadIdx.x;
    const int b   = blockIdx.x / CTAS_PER_B;
    const int c   = blockIdx.x % CTAS_PER_B;
    const float* base = pts + (size_t)b * NPTS * NCH;
    const int p0 = c * NPC;

    // Stage this CTA's xyz slice into SMEM (linear layout; one-time cost).
    for (int i = tid; i < NPC; i += THREADS) {
        const float* r = base + (size_t)(p0 + i) * NCH;
        sx[i] = r[0];
        sy[i] = r[1];
        sz[i] = r[2];
    }

    // Running min-distances in registers.
    float dist[PPT];
#pragma unroll
    for (int j = 0; j < PPT; ++j) dist[j] = __int_as_float(0x7f800000); // +inf

    float qx = base[0], qy = base[1], qz = base[2];
    if (c == 0 && tid < NCH) {
        out[(size_t)b * KSEL * NCH + tid] = base[tid];
    }
    __syncthreads();

    const int lane = tid & 31;
    const int warp = tid >> 5;

    // SMEM viewed as packed float-pairs: element e = points 4e..4e+3.
    const ulonglong2* sx2 = (const ulonglong2*)sx;
    const ulonglong2* sy2 = (const ulonglong2*)sy;
    const ulonglong2* sz2 = (const ulonglong2*)sz;

    for (int it = 1; it < KSEL; ++it) {
        const unsigned long long nqx2 = bcast2(-qx);
        const unsigned long long nqy2 = bcast2(-qy);
        const unsigned long long nqz2 = bcast2(-qz);

        float best = -1.0f;
        unsigned bidx = 0;

#pragma unroll
        for (int g = 0; g < NGROUPS; ++g) {
            const int e = g * THREADS + tid;           // conflict-free: lanes consecutive
            ulonglong2 X = sx2[e];
            ulonglong2 Y = sy2[e];
            ulonglong2 Z = sz2[e];
            const unsigned gi = (unsigned)(p0 + (e << 2));
            const int j = g * 4;

            // pair 0: points gi, gi+1
            {
                unsigned long long dx = add2(X.x, nqx2);
                unsigned long long dy = add2(Y.x, nqy2);
                unsigned long long dz = add2(Z.x, nqz2);
                unsigned long long d2 = fma2(dz, dz, fma2(dx, dx, mul2(dy, dy)));
                float d0, d1; unpack2(d0, d1, d2);
                float n0 = fminf(dist[j + 0], d0); dist[j + 0] = n0;
                if (n0 > best) { best = n0; bidx = gi + 0; }
                float n1 = fminf(dist[j + 1], d1); dist[j + 1] = n1;
                if (n1 > best) { best = n1; bidx = gi + 1; }
            }
            // pair 1: points gi+2, gi+3
            {
                unsigned long long dx = add2(X.y, nqx2);
                unsigned long long dy = add2(Y.y, nqy2);
                unsigned long long dz = add2(Z.y, nqz2);
                unsigned long long d2 = fma2(dz, dz, fma2(dx, dx, mul2(dy, dy)));
                float d0, d1; unpack2(d0, d1, d2);
                float n0 = fminf(dist[j + 2], d0); dist[j + 2] = n0;
                if (n0 > best) { best = n0; bidx = gi + 2; }
                float n1 = fminf(dist[j + 3], d1); dist[j + 3] = n1;
                if (n1 > best) { best = n1; bidx = gi + 3; }
            }
        }

        // Pack (dist_bits << 32) | ~idx : max picks max dist, smallest idx on tie.
        unsigned long long pk =
            ((unsigned long long)__float_as_uint(best) << 32) |
            (unsigned long long)(~bidx);

#pragma unroll
        for (int off = 16; off > 0; off >>= 1) {
            unsigned long long o = __shfl_down_sync(0xffffffffu, pk, off);
            if (o > pk) pk = o;
        }
        if (lane == 0) sred[warp] = pk;
        __syncthreads();

        if (warp == 0) {
            unsigned long long v = (lane < NWARPS) ? sred[lane] : 0ULL;
#pragma unroll
            for (int off = 8; off > 0; off >>= 1) {
                unsigned long long o = __shfl_down_sync(0xffffffffu, v, off);
                if (o > v) v = o;
            }
            if (lane == 0) {
                atomicMax(&g_slot[b][it], v);
                __threadfence();
                atomicAdd(&g_arrive[b][it], 1u);
                while (ld_acq_u32(&g_arrive[b][it]) < CTAS_PER_B) { }
                unsigned long long w = ld_acq_u64(&g_slot[b][it]);
                unsigned widx = ~(unsigned)(w & 0xffffffffULL);
                const float* r = base + (size_t)widx * NCH;
                sq[0] = r[0];
                sq[1] = r[1];
                sq[2] = r[2];
                sidx  = widx;
            }
        }
        __syncthreads();

        qx = sq[0]; qy = sq[1]; qz = sq[2];

        if (c == 0 && tid < NCH) {
            out[((size_t)b * KSEL + it) * NCH + tid] =
                base[(size_t)sidx * NCH + tid];
        }
    }
}

extern "C" void kernel_launch(void* const* d_in, const int* in_sizes, int n_in,
                              void* d_out, int out_size) {
    const float* pts = (const float*)d_in[0];
    float* out = (float*)d_out;

    static bool attr_set = false;
    if (!attr_set) {
        cudaFuncSetAttribute(fps_kernel,
                             cudaFuncAttributeMaxDynamicSharedMemorySize,
                             3 * NPC * sizeof(float));
        attr_set = true;
    }

    fps_init_kernel<<<(BATCH * KSEL + 255) / 256, 256>>>();
    fps_kernel<<<BATCH * CTAS_PER_B, THREADS, 3 * NPC * sizeof(float)>>>(pts, out);
}